// round 1
// baseline (speedup 1.0000x reference)
#include <cuda_runtime.h>
#include <cuda_bf16.h>
#include <cstdint>

// Problem constants
#define BATCH 128
#define SEQT  512
#define DIN   1024
#define HID   128
#define GATES 512         // 4*HID
#define NCLS  8

// ---------------- scratch buffers (device globals; no allocation) ----------------
__device__ float g_xg[(size_t)BATCH * SEQT * GATES];   // 128 MB, reused for both layers
__device__ float g_h1[(size_t)BATCH * SEQT * HID];     // 32 MB  (layer-0 hidden states)
__device__ float g_hlast[BATCH * HID];                 // final layer-1 hidden state

// ---------------- activation helpers (fast, overflow-safe) ----------------
__device__ __forceinline__ float sigmoidf_(float x) {
    return __fdividef(1.0f, 1.0f + __expf(-x));
}
__device__ __forceinline__ float tanhf_(float x) {
    float a = __expf(2.0f * fabsf(x));          // inf ok
    float r = 1.0f - __fdividef(2.0f, 1.0f + a);
    return copysignf(r, x);
}

// ---------------- tiled fp32 GEMM:  C[m][n] = sum_k A[m][k]*B[n][k] + b1[n]+b2[n] ----------------
// A: [M,K] row-major, B: [N,K] row-major (TN layout), C: [M,N]
#define BM 128
#define BN 64
#define BK 16
#define GT 256          // threads
#define AS_STRIDE 132   // padded (16B-aligned stride, bank-shifted)
#define BS_STRIDE 72

__global__ __launch_bounds__(GT) void gemm_bias_kernel(
    const float* __restrict__ A, const float* __restrict__ B,
    const float* __restrict__ b1, const float* __restrict__ b2,
    float* __restrict__ C, int M, int N, int K)
{
    __shared__ float As[BK * AS_STRIDE];
    __shared__ float Bs[BK * BS_STRIDE];

    const int tid = threadIdx.x;
    const int tx = tid & 15;   // n group
    const int ty = tid >> 4;   // m group
    const int m0 = blockIdx.y * BM;
    const int n0 = blockIdx.x * BN;

    // A-tile load mapping: 512 float4 per tile -> 2 per thread
    const int a_row0 = tid >> 2;          // 0..63
    const int a_c4   = tid & 3;           // 0..3
    // B-tile: 256 float4 -> 1 per thread
    const int b_row = tid >> 2;           // 0..63
    const int b_c4  = tid & 3;

    float acc[8][4];
#pragma unroll
    for (int i = 0; i < 8; i++)
#pragma unroll
        for (int j = 0; j < 4; j++) acc[i][j] = 0.0f;

    const int ktiles = K / BK;
    for (int kt = 0; kt < ktiles; kt++) {
        const int k0 = kt * BK;
        // load A tile (128 x 16)
        {
            float4 v0 = *(const float4*)(A + (size_t)(m0 + a_row0) * K + k0 + a_c4 * 4);
            float4 v1 = *(const float4*)(A + (size_t)(m0 + a_row0 + 64) * K + k0 + a_c4 * 4);
            const float* p0 = &v0.x;
            const float* p1 = &v1.x;
#pragma unroll
            for (int u = 0; u < 4; u++) {
                As[(a_c4 * 4 + u) * AS_STRIDE + a_row0]      = p0[u];
                As[(a_c4 * 4 + u) * AS_STRIDE + a_row0 + 64] = p1[u];
            }
        }
        // load B tile (64 x 16)
        {
            float4 v = *(const float4*)(B + (size_t)(n0 + b_row) * K + k0 + b_c4 * 4);
            const float* p = &v.x;
#pragma unroll
            for (int u = 0; u < 4; u++)
                Bs[(b_c4 * 4 + u) * BS_STRIDE + b_row] = p[u];
        }
        __syncthreads();

#pragma unroll
        for (int k = 0; k < BK; k++) {
            float4 a0 = *(const float4*)&As[k * AS_STRIDE + ty * 8];
            float4 a1 = *(const float4*)&As[k * AS_STRIDE + ty * 8 + 4];
            float4 bv = *(const float4*)&Bs[k * BS_STRIDE + tx * 4];
            float av[8] = {a0.x, a0.y, a0.z, a0.w, a1.x, a1.y, a1.z, a1.w};
            float bb[4] = {bv.x, bv.y, bv.z, bv.w};
#pragma unroll
            for (int i = 0; i < 8; i++)
#pragma unroll
                for (int j = 0; j < 4; j++)
                    acc[i][j] += av[i] * bb[j];
        }
        __syncthreads();
    }

    // epilogue: add biases, store
    float bias[4];
#pragma unroll
    for (int j = 0; j < 4; j++) {
        int n = n0 + tx * 4 + j;
        bias[j] = __ldg(&b1[n]) + __ldg(&b2[n]);
    }
#pragma unroll
    for (int i = 0; i < 8; i++) {
        int m = m0 + ty * 8 + i;
        float4 o;
        o.x = acc[i][0] + bias[0];
        o.y = acc[i][1] + bias[1];
        o.z = acc[i][2] + bias[2];
        o.w = acc[i][3] + bias[3];
        *(float4*)(C + (size_t)m * N + n0 + tx * 4) = o;
    }
}

// ---------------- LSTM recurrence ----------------
// One CTA per batch element. 512 threads = one per gate.
// w_hh[g][0:64]   -> per-thread registers (exact fp32)
// w_hh[g][64:128] -> shared memory, layout sw[kc][g] (float4), conflict-free
// smem: sw (128KB) + h_s (512B) + gates (2KB) = 133,632 B dynamic
#define REC_SMEM (16 * 512 * 16 + 128 * 4 + 512 * 4)

__global__ __launch_bounds__(512, 1) void lstm_rec_kernel(
    const float* __restrict__ xg,      // [B, T, 512]
    const float* __restrict__ w_hh,    // [512, 128]
    float* __restrict__ hout,          // [B, T, 128] or nullptr
    float* __restrict__ hlast,         // [B, 128] or nullptr
    int T)
{
    extern __shared__ float smem[];
    float4* sw   = (float4*)smem;            // 16*512 float4
    float* h_s   = smem + 16 * 512 * 4;      // 128 floats
    float* gates = h_s + 128;                // 512 floats

    const int g = threadIdx.x;
    const int b = blockIdx.x;

    // load weights: lower-K half to registers, upper-K half to smem
    const float4* wrow = (const float4*)(w_hh + (size_t)g * HID);
    float4 wreg[16];
#pragma unroll
    for (int i = 0; i < 16; i++) wreg[i] = wrow[i];          // k = 0..63
#pragma unroll
    for (int kc = 0; kc < 16; kc++) sw[kc * 512 + g] = wrow[16 + kc];  // k = 64..127

    if (g < HID) h_s[g] = 0.0f;
    float c = 0.0f;
    __syncthreads();

    const float* xg_b = xg + ((size_t)b * T) * GATES + g;
    float xg_cur = xg_b[0];

    for (int t = 0; t < T; t++) {
        // prefetch next timestep's input contribution
        float xg_nxt = (t + 1 < T) ? xg_b[(size_t)(t + 1) * GATES] : 0.0f;

        float acc = xg_cur;
        const float4* h4 = (const float4*)h_s;
        // register-weight half (k = 0..63)
#pragma unroll
        for (int i = 0; i < 16; i++) {
            float4 hv = h4[i];
            float4 wv = wreg[i];
            acc += hv.x * wv.x + hv.y * wv.y + hv.z * wv.z + hv.w * wv.w;
        }
        // smem-weight half (k = 64..127)
#pragma unroll
        for (int kc = 0; kc < 16; kc++) {
            float4 hv = h4[16 + kc];
            float4 wv = sw[kc * 512 + g];
            acc += hv.x * wv.x + hv.y * wv.y + hv.z * wv.z + hv.w * wv.w;
        }
        gates[g] = acc;
        __syncthreads();

        if (g < HID) {
            float ig = sigmoidf_(gates[g]);
            float fg = sigmoidf_(gates[HID + g]);
            float gg = tanhf_(gates[2 * HID + g]);
            float og = sigmoidf_(gates[3 * HID + g]);
            c = fg * c + ig * gg;
            float h = og * tanhf_(c);
            h_s[g] = h;
            if (hout) hout[((size_t)b * T + t) * HID + g] = h;
        }
        __syncthreads();
        xg_cur = xg_nxt;
    }

    if (hlast && g < HID) hlast[b * HID + g] = h_s[g];
}

// ---------------- final FC:  logits[b][c] = h_last[b] . fc_w[c] + fc_b[c] ----------------
__global__ void fc_kernel(const float* __restrict__ hlast,
                          const float* __restrict__ fc_w,
                          const float* __restrict__ fc_b,
                          float* __restrict__ out)
{
    int tid = threadIdx.x;              // 1024 threads: b*8 + cls
    int b = tid >> 3;
    int cls = tid & 7;
    const float* hv = hlast + b * HID;
    const float* wv = fc_w + cls * HID;
    float s = fc_b[cls];
#pragma unroll 8
    for (int j = 0; j < HID; j++) s += hv[j] * wv[j];
    out[b * NCLS + cls] = s;
}

// ---------------- launch ----------------
extern "C" void kernel_launch(void* const* d_in, const int* in_sizes, int n_in,
                              void* d_out, int out_size)
{
    const float* x     = (const float*)d_in[0];
    const float* w_ih0 = (const float*)d_in[1];
    const float* w_hh0 = (const float*)d_in[2];
    const float* b_ih0 = (const float*)d_in[3];
    const float* b_hh0 = (const float*)d_in[4];
    const float* w_ih1 = (const float*)d_in[5];
    const float* w_hh1 = (const float*)d_in[6];
    const float* b_ih1 = (const float*)d_in[7];
    const float* b_hh1 = (const float*)d_in[8];
    const float* fc_w  = (const float*)d_in[9];
    const float* fc_b  = (const float*)d_in[10];
    float* out = (float*)d_out;

    float *xg_p = nullptr, *h1_p = nullptr, *hl_p = nullptr;
    cudaGetSymbolAddress((void**)&xg_p, g_xg);
    cudaGetSymbolAddress((void**)&h1_p, g_h1);
    cudaGetSymbolAddress((void**)&hl_p, g_hlast);

    // opt-in large dynamic smem for recurrence (idempotent; non-stream API)
    cudaFuncSetAttribute(lstm_rec_kernel,
                         cudaFuncAttributeMaxDynamicSharedMemorySize, REC_SMEM);

    const int M = BATCH * SEQT;   // 65536

    // 1) layer-0 input GEMM: xg0 = x @ w_ih0^T + b_ih0 + b_hh0
    {
        dim3 grid(GATES / BN, M / BM);
        gemm_bias_kernel<<<grid, GT>>>(x, w_ih0, b_ih0, b_hh0, xg_p, M, GATES, DIN);
    }
    // 2) layer-0 recurrence -> h1
    lstm_rec_kernel<<<BATCH, 512, REC_SMEM>>>(xg_p, w_hh0, h1_p, nullptr, SEQT);
    // 3) layer-1 input GEMM: xg1 = h1 @ w_ih1^T + b_ih1 + b_hh1 (reuse xg buffer)
    {
        dim3 grid(GATES / BN, M / BM);
        gemm_bias_kernel<<<grid, GT>>>(h1_p, w_ih1, b_ih1, b_hh1, xg_p, M, GATES, HID);
    }
    // 4) layer-1 recurrence -> h_last only
    lstm_rec_kernel<<<BATCH, 512, REC_SMEM>>>(xg_p, w_hh1, nullptr, hl_p, SEQT);
    // 5) FC head
    fc_kernel<<<1, BATCH * NCLS>>>(hl_p, fc_w, fc_b, out);
}

// round 6
// speedup vs baseline: 1.5582x; 1.5582x over previous
#include <cuda_runtime.h>
#include <cuda_fp16.h>
#include <cstdint>

// Problem constants
#define BATCH 128
#define SEQT  512
#define DIN   1024
#define HID   128
#define GATES 512
#define NCLS  8
#define MTOT  (BATCH * SEQT)      // 65536
#define MTILES (MTOT / 128)       // 512
#define NCH0  48                  // 3*1024/64 k-chunks, layer 0
#define NCH1  6                   // 3*128/64  k-chunks, layer 1

// ---------------- scratch (device globals; no allocation) ----------------
__device__ __align__(1024) __half g_as[(size_t)MTILES * NCH0 * 8192];  // 384MB split-fp16 A tiles
__device__ __align__(1024) __half g_bs0[(size_t)NCH0 * 32768];         // 3MB  split-fp16 W_ih0
__device__ __align__(1024) __half g_bs1[(size_t)NCH1 * 32768];         // 384KB split-fp16 W_ih1
__device__ float g_xg[(size_t)MTOT * GATES];   // 128MB gate pre-activations
__device__ float g_h1[(size_t)MTOT * HID];     // 32MB layer-0 hidden states
__device__ float g_hlast[BATCH * HID];

// ---------------- PTX helpers (all sm_103 baseline; NO tcgen05) ----------------
__device__ __forceinline__ uint32_t smem_u32(const void* p) {
    uint32_t a;
    asm("{ .reg .u64 t; cvta.to.shared.u64 t, %1; cvt.u32.u64 %0, t; }" : "=r"(a) : "l"(p));
    return a;
}
__device__ __forceinline__ void mbar_init(uint32_t m, uint32_t cnt) {
    asm volatile("mbarrier.init.shared.b64 [%0], %1;" :: "r"(m), "r"(cnt) : "memory");
}
__device__ __forceinline__ void mbar_expect_tx(uint32_t m, uint32_t b) {
    asm volatile("mbarrier.arrive.expect_tx.shared.b64 _, [%0], %1;" :: "r"(m), "r"(b) : "memory");
}
__device__ __forceinline__ void mbar_wait(uint32_t m, uint32_t ph) {
    asm volatile(
        "{\n\t.reg .pred P;\n\t"
        "WL_%=:\n\t"
        "mbarrier.try_wait.parity.shared.b64 P, [%0], %1;\n\t"
        "@P bra WD_%=;\n\t"
        "bra WL_%=;\n\t"
        "WD_%=:\n\t}"
        :: "r"(m), "r"(ph) : "memory");
}
__device__ __forceinline__ void bulk_g2s(uint32_t dst, const void* src, uint32_t bytes, uint32_t mbar) {
    asm volatile(
        "cp.async.bulk.shared::cluster.global.mbarrier::complete_tx::bytes [%0], [%1], %2, [%3];"
        :: "r"(dst), "l"(src), "r"(bytes), "r"(mbar) : "memory");
}
__device__ __forceinline__ void ldsm_x4(uint32_t& r0, uint32_t& r1, uint32_t& r2, uint32_t& r3,
                                        uint32_t a) {
    asm volatile("ldmatrix.sync.aligned.m8n8.x4.shared.b16 {%0,%1,%2,%3}, [%4];"
        : "=r"(r0), "=r"(r1), "=r"(r2), "=r"(r3) : "r"(a));
}
__device__ __forceinline__ void mma16816(float& d0, float& d1, float& d2, float& d3,
                                         uint32_t a0, uint32_t a1, uint32_t a2, uint32_t a3,
                                         uint32_t b0, uint32_t b1) {
    asm volatile("mma.sync.aligned.m16n8k16.row.col.f32.f16.f16.f32 "
        "{%0,%1,%2,%3},{%4,%5,%6,%7},{%8,%9},{%0,%1,%2,%3};"
        : "+f"(d0), "+f"(d1), "+f"(d2), "+f"(d3)
        : "r"(a0), "r"(a1), "r"(a2), "r"(a3), "r"(b0), "r"(b1));
}

// ---------------- split-fp16 packing ----------------
__device__ __forceinline__ uint32_t pk2(float f0, float f1, bool lo) {
    __half h0 = __float2half_rn(f0);
    __half h1 = __float2half_rn(f1);
    if (lo) {
        h0 = __float2half_rn(f0 - __half2float(h0));
        h1 = __float2half_rn(f1 - __half2float(h1));
    }
    __half2 p = __halves2half2(h0, h1);
    return *reinterpret_cast<uint32_t*>(&p);
}

// ---------------- conversion: activations -> tiled+swizzled split-fp16 ----------------
// A' layout: [mt (128-row tile)][chunk][128 rows x 64 fp16, SW128-swizzled] (16KB tiles)
// slabs along logical K' = 3K: [hi | hi | lo]
__global__ void conv_a_kernel(const float* __restrict__ src, __half* __restrict__ dst,
                              int nchunk, int kshift)
{
    int idx = blockIdx.x * 256 + threadIdx.x;
    int u  = idx & 1023;
    int t2 = idx >> 10;
    int c  = t2 % nchunk;
    int mt = t2 / nchunk;
    int r = u >> 3, g = u & 7;
    int kk = c * 64 + g * 8;
    int slab = kk >> kshift;
    int k = kk - (slab << kshift);
    const float* xr = src + (((size_t)(mt * 128 + r)) << kshift) + k;
    float4 v0 = *(const float4*)xr;
    float4 v1 = *(const float4*)(xr + 4);
    bool lo = (slab == 2);
    uint4 o;
    o.x = pk2(v0.x, v0.y, lo);
    o.y = pk2(v0.z, v0.w, lo);
    o.z = pk2(v1.x, v1.y, lo);
    o.w = pk2(v1.z, v1.w, lo);
    uint32_t ob = (uint32_t)((r << 7) | (g << 4));
    uint32_t so = ob ^ ((ob >> 3) & 0x70);
    char* tile = (char*)(dst + (((size_t)(mt * nchunk + c)) << 13));
    *(uint4*)(tile + so) = o;
}

// weights -> [chunk][512 rows x 64 fp16, SW128-swizzled] (64KB chunks)
// slabs along K': [hi | lo | hi]  (pairs with A's [hi | hi | lo])
__global__ void conv_b_kernel(const float* __restrict__ w, __half* __restrict__ dst,
                              int kshift)
{
    int idx = blockIdx.x * 256 + threadIdx.x;
    int g = idx & 7;
    int n = (idx >> 3) & 511;
    int c = idx >> 12;
    int kk = c * 64 + g * 8;
    int slab = kk >> kshift;
    int k = kk - (slab << kshift);
    const float* wr = w + (((size_t)n) << kshift) + k;
    float4 v0 = *(const float4*)wr;
    float4 v1 = *(const float4*)(wr + 4);
    bool lo = (slab == 1);
    uint4 o;
    o.x = pk2(v0.x, v0.y, lo);
    o.y = pk2(v0.z, v0.w, lo);
    o.z = pk2(v1.x, v1.y, lo);
    o.w = pk2(v1.z, v1.w, lo);
    uint32_t ob = (uint32_t)((n << 7) | (g << 4));
    uint32_t so = ob ^ ((ob >> 3) & 0x70);
    char* chunk = (char*)(dst + (((size_t)c) << 15));
    *(uint4*)(chunk + so) = o;
}

// ---------------- HMMA GEMM: C[128 rows x 256 gates] per CTA ----------------
// 512 threads = 16 warps (4M x 4N), warp tile 32x64, mma.sync.m16n8k16 fp16->f32.
// 3-stage cp.async.bulk pipeline; stage = A tile (16KB) + B half-chunk (32KB).
#define GEMM_SMEM 152576
__global__ __launch_bounds__(512, 1) void gemm_hmma_kernel(
    const __half* __restrict__ Ap, const __half* __restrict__ Bp,
    const float* __restrict__ b1, const float* __restrict__ b2,
    float* __restrict__ C, int nchunk)
{
    extern __shared__ char smem_raw[];
    uint32_t sb0 = smem_u32(smem_raw);
    uint32_t ab = (sb0 + 1023) & ~1023u;                 // 1024-aligned base
    float* smbias = (float*)(smem_raw + (ab - sb0));     // 512 floats at offset 0
    // mbarriers at ab+2048 (+8 per stage); stages at ab+4096 + s*49152

    const int tid = threadIdx.x;
    const int lane = tid & 31, wid = tid >> 5;
    const int wm = wid >> 2, wn = wid & 3;
    const int sub = lane >> 3, l7 = lane & 7;

    if (tid < 512) smbias[tid] = b1[tid] + b2[tid];
    if (tid == 0) {
        mbar_init(ab + 2048, 1); mbar_init(ab + 2056, 1); mbar_init(ab + 2064, 1);
    }
    __syncthreads();

    const int mt = blockIdx.x >> 1, j = blockIdx.x & 1;
    const char* Asrc = (const char*)Ap + ((size_t)mt * nchunk) * 16384;
    const char* Bsrc = (const char*)Bp + (size_t)j * 32768;

    if (tid == 0) {
        int npre = nchunk < 3 ? nchunk : 3;
        for (int c = 0; c < npre; c++) {
            uint32_t st = ab + 4096 + c * 49152;
            uint32_t mb = ab + 2048 + c * 8;
            mbar_expect_tx(mb, 49152);
            bulk_g2s(st,         Asrc + (size_t)c * 16384, 16384, mb);
            bulk_g2s(st + 16384, Bsrc + (size_t)c * 65536, 32768, mb);
        }
    }

    float acc[2][8][4];
#pragma unroll
    for (int a = 0; a < 2; a++)
#pragma unroll
        for (int b = 0; b < 8; b++)
#pragma unroll
            for (int d = 0; d < 4; d++) acc[a][b][d] = 0.0f;

    // ldmatrix address components (SW128: kb ^ ((row&7)<<4), row&7 == l7)
    const uint32_t xorv = (uint32_t)(l7 << 4);
    const uint32_t arow = (uint32_t)((wm * 32 + (sub & 1) * 8 + l7) * 128); // mb=0; +2048 for mb=1
    const uint32_t akh  = (uint32_t)((sub >> 1) * 16);
    const uint32_t brow = (uint32_t)((wn * 64 + (sub >> 1) * 8 + l7) * 128); // nb2=0; +2048 per nb2
    const uint32_t bkh  = (uint32_t)((sub & 1) * 16);

    for (int c = 0; c < nchunk; c++) {
        int s = c % 3;
        uint32_t ph = (uint32_t)((c / 3) & 1);
        uint32_t mb_full = ab + 2048 + s * 8;
        mbar_wait(mb_full, ph);
        uint32_t Abase = ab + 4096 + s * 49152;
        uint32_t Bbase = Abase + 16384;

#pragma unroll
        for (int ks = 0; ks < 4; ks++) {
            uint32_t ak = ((uint32_t)(ks * 32) + akh) ^ xorv;
            uint32_t bk = ((uint32_t)(ks * 32) + bkh) ^ xorv;
            uint32_t a0[4], a1[4], bf[4][4];
            ldsm_x4(a0[0], a0[1], a0[2], a0[3], Abase + arow + ak);
            ldsm_x4(a1[0], a1[1], a1[2], a1[3], Abase + arow + 2048 + ak);
#pragma unroll
            for (int nb2 = 0; nb2 < 4; nb2++)
                ldsm_x4(bf[nb2][0], bf[nb2][1], bf[nb2][2], bf[nb2][3],
                        Bbase + brow + nb2 * 2048 + bk);
#pragma unroll
            for (int nb = 0; nb < 8; nb++) {
                uint32_t bb0 = bf[nb >> 1][(nb & 1) * 2];
                uint32_t bb1 = bf[nb >> 1][(nb & 1) * 2 + 1];
                mma16816(acc[0][nb][0], acc[0][nb][1], acc[0][nb][2], acc[0][nb][3],
                         a0[0], a0[1], a0[2], a0[3], bb0, bb1);
                mma16816(acc[1][nb][0], acc[1][nb][1], acc[1][nb][2], acc[1][nb][3],
                         a1[0], a1[1], a1[2], a1[3], bb0, bb1);
            }
        }
        __syncthreads();
        if (tid == 0 && c + 3 < nchunk) {
            uint32_t st = ab + 4096 + s * 49152;
            mbar_expect_tx(mb_full, 49152);
            bulk_g2s(st,         Asrc + (size_t)(c + 3) * 16384, 16384, mb_full);
            bulk_g2s(st + 16384, Bsrc + (size_t)(c + 3) * 65536, 32768, mb_full);
        }
    }

    // epilogue: bias add + store (32B-sector friendly)
    const int mbase = mt * 128 + wm * 32 + (lane >> 2);
    const int colb  = j * 256 + wn * 64 + (lane & 3) * 2;
#pragma unroll
    for (int mb = 0; mb < 2; mb++)
#pragma unroll
        for (int nb = 0; nb < 8; nb++) {
            int cc = colb + nb * 8;
            float bx = smbias[cc], by = smbias[cc + 1];
            size_t r0 = (size_t)(mbase + mb * 16) * GATES + cc;
            float2 v0 = make_float2(acc[mb][nb][0] + bx, acc[mb][nb][1] + by);
            float2 v1 = make_float2(acc[mb][nb][2] + bx, acc[mb][nb][3] + by);
            *(float2*)(C + r0) = v0;
            *(float2*)(C + r0 + (size_t)8 * GATES) = v1;
        }
}

// ---------------- activations ----------------
__device__ __forceinline__ float sigmoidf_(float x) {
    return __fdividef(1.0f, 1.0f + __expf(-x));
}
__device__ __forceinline__ float tanhf_(float x) {
    float a = __expf(2.0f * fabsf(x));
    float r = 1.0f - __fdividef(2.0f, 1.0f + a);
    return copysignf(r, x);
}

// ---------------- LSTM recurrence (unchanged, proven) ----------------
#define REC_SMEM (16 * 512 * 16 + 128 * 4 + 512 * 4)
__global__ __launch_bounds__(512, 1) void lstm_rec_kernel(
    const float* __restrict__ xg, const float* __restrict__ w_hh,
    float* __restrict__ hout, float* __restrict__ hlast, int T)
{
    extern __shared__ float smem[];
    float4* sw = (float4*)smem;
    float* h_s = smem + 16 * 512 * 4;
    float* gates = h_s + 128;

    const int g = threadIdx.x;
    const int b = blockIdx.x;

    const float4* wrow = (const float4*)(w_hh + (size_t)g * HID);
    float4 wreg[16];
#pragma unroll
    for (int i = 0; i < 16; i++) wreg[i] = wrow[i];
#pragma unroll
    for (int kc = 0; kc < 16; kc++) sw[kc * 512 + g] = wrow[16 + kc];

    if (g < HID) h_s[g] = 0.0f;
    float c = 0.0f;
    __syncthreads();

    const float* xg_b = xg + ((size_t)b * T) * GATES + g;
    float xg_cur = xg_b[0];

    for (int t = 0; t < T; t++) {
        float xg_nxt = (t + 1 < T) ? xg_b[(size_t)(t + 1) * GATES] : 0.0f;
        float acc = xg_cur;
        const float4* h4 = (const float4*)h_s;
#pragma unroll
        for (int i = 0; i < 16; i++) {
            float4 hv = h4[i]; float4 wv = wreg[i];
            acc += hv.x * wv.x + hv.y * wv.y + hv.z * wv.z + hv.w * wv.w;
        }
#pragma unroll
        for (int kc = 0; kc < 16; kc++) {
            float4 hv = h4[16 + kc]; float4 wv = sw[kc * 512 + g];
            acc += hv.x * wv.x + hv.y * wv.y + hv.z * wv.z + hv.w * wv.w;
        }
        gates[g] = acc;
        __syncthreads();

        if (g < HID) {
            float ig = sigmoidf_(gates[g]);
            float fg = sigmoidf_(gates[HID + g]);
            float gg = tanhf_(gates[2 * HID + g]);
            float og = sigmoidf_(gates[3 * HID + g]);
            c = fg * c + ig * gg;
            float h = og * tanhf_(c);
            h_s[g] = h;
            if (hout) hout[((size_t)b * T + t) * HID + g] = h;
        }
        __syncthreads();
        xg_cur = xg_nxt;
    }
    if (hlast && g < HID) hlast[b * HID + g] = h_s[g];
}

// ---------------- final FC ----------------
__global__ void fc_kernel(const float* __restrict__ hlast, const float* __restrict__ fc_w,
                          const float* __restrict__ fc_b, float* __restrict__ out)
{
    int tid = threadIdx.x;
    int b = tid >> 3;
    int cls = tid & 7;
    const float* hv = hlast + b * HID;
    const float* wv = fc_w + cls * HID;
    float s = fc_b[cls];
#pragma unroll 8
    for (int j = 0; j < HID; j++) s += hv[j] * wv[j];
    out[b * NCLS + cls] = s;
}

// ---------------- launch ----------------
extern "C" void kernel_launch(void* const* d_in, const int* in_sizes, int n_in,
                              void* d_out, int out_size)
{
    const float* x     = (const float*)d_in[0];
    const float* w_ih0 = (const float*)d_in[1];
    const float* w_hh0 = (const float*)d_in[2];
    const float* b_ih0 = (const float*)d_in[3];
    const float* b_hh0 = (const float*)d_in[4];
    const float* w_ih1 = (const float*)d_in[5];
    const float* w_hh1 = (const float*)d_in[6];
    const float* b_ih1 = (const float*)d_in[7];
    const float* b_hh1 = (const float*)d_in[8];
    const float* fc_w  = (const float*)d_in[9];
    const float* fc_b  = (const float*)d_in[10];
    float* out = (float*)d_out;

    float *xg_p = nullptr, *h1_p = nullptr, *hl_p = nullptr;
    __half *as_p = nullptr, *bs0_p = nullptr, *bs1_p = nullptr;
    cudaGetSymbolAddress((void**)&xg_p, g_xg);
    cudaGetSymbolAddress((void**)&h1_p, g_h1);
    cudaGetSymbolAddress((void**)&hl_p, g_hlast);
    cudaGetSymbolAddress((void**)&as_p, g_as);
    cudaGetSymbolAddress((void**)&bs0_p, g_bs0);
    cudaGetSymbolAddress((void**)&bs1_p, g_bs1);

    cudaFuncSetAttribute(lstm_rec_kernel,
                         cudaFuncAttributeMaxDynamicSharedMemorySize, REC_SMEM);
    cudaFuncSetAttribute(gemm_hmma_kernel,
                         cudaFuncAttributeMaxDynamicSharedMemorySize, GEMM_SMEM);

    // weight conversions (tiny)
    conv_b_kernel<<<NCH0 * 512 * 8 / 256, 256>>>(w_ih0, bs0_p, 10);
    conv_b_kernel<<<NCH1 * 512 * 8 / 256, 256>>>(w_ih1, bs1_p, 7);

    // layer 0: x -> split-fp16 tiles -> HMMA GEMM -> recurrence
    conv_a_kernel<<<MTILES * NCH0 * 1024 / 256, 256>>>(x, as_p, NCH0, 10);
    gemm_hmma_kernel<<<MTILES * 2, 512, GEMM_SMEM>>>(as_p, bs0_p, b_ih0, b_hh0, xg_p, NCH0);
    lstm_rec_kernel<<<BATCH, 512, REC_SMEM>>>(xg_p, w_hh0, h1_p, nullptr, SEQT);

    // layer 1: h1 -> split-fp16 tiles -> HMMA GEMM -> recurrence
    conv_a_kernel<<<MTILES * NCH1 * 1024 / 256, 256>>>(h1_p, as_p, NCH1, 7);
    gemm_hmma_kernel<<<MTILES * 2, 512, GEMM_SMEM>>>(as_p, bs1_p, b_ih1, b_hh1, xg_p, NCH1);
    lstm_rec_kernel<<<BATCH, 512, REC_SMEM>>>(xg_p, w_hh1, nullptr, hl_p, SEQT);

    // FC head
    fc_kernel<<<1, BATCH * NCLS>>>(hl_p, fc_w, fc_b, out);
}

// round 7
// speedup vs baseline: 1.8127x; 1.1633x over previous
#include <cuda_runtime.h>
#include <cuda_fp16.h>
#include <cstdint>

// Problem constants
#define BATCH 128
#define SEQT  512
#define DIN   1024
#define HID   128
#define GATES 512
#define NCLS  8
#define MTOT  (BATCH * SEQT)      // 65536
#define MTILES (MTOT / 128)       // 512
#define NCH0  48                  // 3*1024/64 k-chunks, layer 0
#define NCH1  6                   // 3*128/64  k-chunks, layer 1

// ---------------- scratch (device globals; no allocation) ----------------
__device__ __align__(1024) __half g_as[(size_t)MTILES * NCH0 * 8192];  // 384MB split-fp16 A tiles
__device__ __align__(1024) __half g_bs0[(size_t)NCH0 * 32768];         // 3MB  split-fp16 W_ih0
__device__ __align__(1024) __half g_bs1[(size_t)NCH1 * 32768];         // 384KB split-fp16 W_ih1
__device__ float g_xg[(size_t)MTOT * GATES];   // 128MB gate pre-activations
__device__ float g_h1[(size_t)MTOT * HID];     // 32MB layer-0 hidden states
__device__ float g_hlast[BATCH * HID];

// ---------------- PTX helpers (all sm_103 baseline; NO tcgen05) ----------------
__device__ __forceinline__ uint32_t smem_u32(const void* p) {
    uint32_t a;
    asm("{ .reg .u64 t; cvta.to.shared.u64 t, %1; cvt.u32.u64 %0, t; }" : "=r"(a) : "l"(p));
    return a;
}
__device__ __forceinline__ void mbar_init(uint32_t m, uint32_t cnt) {
    asm volatile("mbarrier.init.shared.b64 [%0], %1;" :: "r"(m), "r"(cnt) : "memory");
}
__device__ __forceinline__ void mbar_expect_tx(uint32_t m, uint32_t b) {
    asm volatile("mbarrier.arrive.expect_tx.shared.b64 _, [%0], %1;" :: "r"(m), "r"(b) : "memory");
}
__device__ __forceinline__ void mbar_wait(uint32_t m, uint32_t ph) {
    asm volatile(
        "{\n\t.reg .pred P;\n\t"
        "WL_%=:\n\t"
        "mbarrier.try_wait.parity.shared.b64 P, [%0], %1;\n\t"
        "@P bra WD_%=;\n\t"
        "bra WL_%=;\n\t"
        "WD_%=:\n\t}"
        :: "r"(m), "r"(ph) : "memory");
}
__device__ __forceinline__ void bulk_g2s(uint32_t dst, const void* src, uint32_t bytes, uint32_t mbar) {
    asm volatile(
        "cp.async.bulk.shared::cluster.global.mbarrier::complete_tx::bytes [%0], [%1], %2, [%3];"
        :: "r"(dst), "l"(src), "r"(bytes), "r"(mbar) : "memory");
}
__device__ __forceinline__ void ldsm_x4(uint32_t& r0, uint32_t& r1, uint32_t& r2, uint32_t& r3,
                                        uint32_t a) {
    asm volatile("ldmatrix.sync.aligned.m8n8.x4.shared.b16 {%0,%1,%2,%3}, [%4];"
        : "=r"(r0), "=r"(r1), "=r"(r2), "=r"(r3) : "r"(a));
}
__device__ __forceinline__ void mma16816(float& d0, float& d1, float& d2, float& d3,
                                         uint32_t a0, uint32_t a1, uint32_t a2, uint32_t a3,
                                         uint32_t b0, uint32_t b1) {
    asm volatile("mma.sync.aligned.m16n8k16.row.col.f32.f16.f16.f32 "
        "{%0,%1,%2,%3},{%4,%5,%6,%7},{%8,%9},{%0,%1,%2,%3};"
        : "+f"(d0), "+f"(d1), "+f"(d2), "+f"(d3)
        : "r"(a0), "r"(a1), "r"(a2), "r"(a3), "r"(b0), "r"(b1));
}

// ---- packed f32x2 FMA (Blackwell FFMA2; PTX-gated at sm_100 base, no 'a') ----
typedef unsigned long long u64b;
__device__ __forceinline__ void ffma2(u64b& d, u64b a, u64b b) {
    asm("fma.rn.f32x2 %0, %1, %2, %0;" : "+l"(d) : "l"(a), "l"(b));
}
__device__ __forceinline__ u64b pk64(float x, float y) {
    u64b r; asm("mov.b64 %0, {%1, %2};" : "=l"(r) : "f"(x), "f"(y)); return r;
}
__device__ __forceinline__ float2 upk64(u64b v) {
    float2 r; asm("mov.b64 {%0, %1}, %2;" : "=f"(r.x), "=f"(r.y) : "l"(v)); return r;
}

// ---------------- split-fp16 packing ----------------
__device__ __forceinline__ uint32_t pk2(float f0, float f1, bool lo) {
    __half h0 = __float2half_rn(f0);
    __half h1 = __float2half_rn(f1);
    if (lo) {
        h0 = __float2half_rn(f0 - __half2float(h0));
        h1 = __float2half_rn(f1 - __half2float(h1));
    }
    __half2 p = __halves2half2(h0, h1);
    return *reinterpret_cast<uint32_t*>(&p);
}

// ---------------- conversion: activations -> tiled+swizzled split-fp16 ----------------
// A' layout: [mt (128-row tile)][chunk][128 rows x 64 fp16, SW128-swizzled] (16KB tiles)
// slabs along logical K' = 3K: [hi | hi | lo]
__global__ void conv_a_kernel(const float* __restrict__ src, __half* __restrict__ dst,
                              int nchunk, int kshift)
{
    int idx = blockIdx.x * 256 + threadIdx.x;
    int u  = idx & 1023;
    int t2 = idx >> 10;
    int c  = t2 % nchunk;
    int mt = t2 / nchunk;
    int r = u >> 3, g = u & 7;
    int kk = c * 64 + g * 8;
    int slab = kk >> kshift;
    int k = kk - (slab << kshift);
    const float* xr = src + (((size_t)(mt * 128 + r)) << kshift) + k;
    float4 v0 = *(const float4*)xr;
    float4 v1 = *(const float4*)(xr + 4);
    bool lo = (slab == 2);
    uint4 o;
    o.x = pk2(v0.x, v0.y, lo);
    o.y = pk2(v0.z, v0.w, lo);
    o.z = pk2(v1.x, v1.y, lo);
    o.w = pk2(v1.z, v1.w, lo);
    uint32_t ob = (uint32_t)((r << 7) | (g << 4));
    uint32_t so = ob ^ ((ob >> 3) & 0x70);
    char* tile = (char*)(dst + (((size_t)(mt * nchunk + c)) << 13));
    *(uint4*)(tile + so) = o;
}

// weights -> [chunk][512 rows x 64 fp16, SW128-swizzled] (64KB chunks)
// slabs along K': [hi | lo | hi]  (pairs with A's [hi | hi | lo])
__global__ void conv_b_kernel(const float* __restrict__ w, __half* __restrict__ dst,
                              int kshift)
{
    int idx = blockIdx.x * 256 + threadIdx.x;
    int g = idx & 7;
    int n = (idx >> 3) & 511;
    int c = idx >> 12;
    int kk = c * 64 + g * 8;
    int slab = kk >> kshift;
    int k = kk - (slab << kshift);
    const float* wr = w + (((size_t)n) << kshift) + k;
    float4 v0 = *(const float4*)wr;
    float4 v1 = *(const float4*)(wr + 4);
    bool lo = (slab == 1);
    uint4 o;
    o.x = pk2(v0.x, v0.y, lo);
    o.y = pk2(v0.z, v0.w, lo);
    o.z = pk2(v1.x, v1.y, lo);
    o.w = pk2(v1.z, v1.w, lo);
    uint32_t ob = (uint32_t)((n << 7) | (g << 4));
    uint32_t so = ob ^ ((ob >> 3) & 0x70);
    char* chunk = (char*)(dst + (((size_t)c) << 15));
    *(uint4*)(chunk + so) = o;
}

// ---------------- HMMA GEMM: C[128 rows x 256 gates] per CTA (unchanged, proven) ----------------
#define GEMM_SMEM 152576
__global__ __launch_bounds__(512, 1) void gemm_hmma_kernel(
    const __half* __restrict__ Ap, const __half* __restrict__ Bp,
    const float* __restrict__ b1, const float* __restrict__ b2,
    float* __restrict__ C, int nchunk)
{
    extern __shared__ char smem_raw[];
    uint32_t sb0 = smem_u32(smem_raw);
    uint32_t ab = (sb0 + 1023) & ~1023u;                 // 1024-aligned base
    float* smbias = (float*)(smem_raw + (ab - sb0));     // 512 floats at offset 0

    const int tid = threadIdx.x;
    const int lane = tid & 31, wid = tid >> 5;
    const int wm = wid >> 2, wn = wid & 3;
    const int sub = lane >> 3, l7 = lane & 7;

    if (tid < 512) smbias[tid] = b1[tid] + b2[tid];
    if (tid == 0) {
        mbar_init(ab + 2048, 1); mbar_init(ab + 2056, 1); mbar_init(ab + 2064, 1);
    }
    __syncthreads();

    const int mt = blockIdx.x >> 1, j = blockIdx.x & 1;
    const char* Asrc = (const char*)Ap + ((size_t)mt * nchunk) * 16384;
    const char* Bsrc = (const char*)Bp + (size_t)j * 32768;

    if (tid == 0) {
        int npre = nchunk < 3 ? nchunk : 3;
        for (int c = 0; c < npre; c++) {
            uint32_t st = ab + 4096 + c * 49152;
            uint32_t mb = ab + 2048 + c * 8;
            mbar_expect_tx(mb, 49152);
            bulk_g2s(st,         Asrc + (size_t)c * 16384, 16384, mb);
            bulk_g2s(st + 16384, Bsrc + (size_t)c * 65536, 32768, mb);
        }
    }

    float acc[2][8][4];
#pragma unroll
    for (int a = 0; a < 2; a++)
#pragma unroll
        for (int b = 0; b < 8; b++)
#pragma unroll
            for (int d = 0; d < 4; d++) acc[a][b][d] = 0.0f;

    const uint32_t xorv = (uint32_t)(l7 << 4);
    const uint32_t arow = (uint32_t)((wm * 32 + (sub & 1) * 8 + l7) * 128);
    const uint32_t akh  = (uint32_t)((sub >> 1) * 16);
    const uint32_t brow = (uint32_t)((wn * 64 + (sub >> 1) * 8 + l7) * 128);
    const uint32_t bkh  = (uint32_t)((sub & 1) * 16);

    for (int c = 0; c < nchunk; c++) {
        int s = c % 3;
        uint32_t ph = (uint32_t)((c / 3) & 1);
        uint32_t mb_full = ab + 2048 + s * 8;
        mbar_wait(mb_full, ph);
        uint32_t Abase = ab + 4096 + s * 49152;
        uint32_t Bbase = Abase + 16384;

#pragma unroll
        for (int ks = 0; ks < 4; ks++) {
            uint32_t ak = ((uint32_t)(ks * 32) + akh) ^ xorv;
            uint32_t bk = ((uint32_t)(ks * 32) + bkh) ^ xorv;
            uint32_t a0[4], a1[4], bf[4][4];
            ldsm_x4(a0[0], a0[1], a0[2], a0[3], Abase + arow + ak);
            ldsm_x4(a1[0], a1[1], a1[2], a1[3], Abase + arow + 2048 + ak);
#pragma unroll
            for (int nb2 = 0; nb2 < 4; nb2++)
                ldsm_x4(bf[nb2][0], bf[nb2][1], bf[nb2][2], bf[nb2][3],
                        Bbase + brow + nb2 * 2048 + bk);
#pragma unroll
            for (int nb = 0; nb < 8; nb++) {
                uint32_t bb0 = bf[nb >> 1][(nb & 1) * 2];
                uint32_t bb1 = bf[nb >> 1][(nb & 1) * 2 + 1];
                mma16816(acc[0][nb][0], acc[0][nb][1], acc[0][nb][2], acc[0][nb][3],
                         a0[0], a0[1], a0[2], a0[3], bb0, bb1);
                mma16816(acc[1][nb][0], acc[1][nb][1], acc[1][nb][2], acc[1][nb][3],
                         a1[0], a1[1], a1[2], a1[3], bb0, bb1);
            }
        }
        __syncthreads();
        if (tid == 0 && c + 3 < nchunk) {
            uint32_t st = ab + 4096 + s * 49152;
            mbar_expect_tx(mb_full, 49152);
            bulk_g2s(st,         Asrc + (size_t)(c + 3) * 16384, 16384, mb_full);
            bulk_g2s(st + 16384, Bsrc + (size_t)(c + 3) * 65536, 32768, mb_full);
        }
    }

    const int mbase = mt * 128 + wm * 32 + (lane >> 2);
    const int colb  = j * 256 + wn * 64 + (lane & 3) * 2;
#pragma unroll
    for (int mb = 0; mb < 2; mb++)
#pragma unroll
        for (int nb = 0; nb < 8; nb++) {
            int cc = colb + nb * 8;
            float bx = smbias[cc], by = smbias[cc + 1];
            size_t r0 = (size_t)(mbase + mb * 16) * GATES + cc;
            float2 v0 = make_float2(acc[mb][nb][0] + bx, acc[mb][nb][1] + by);
            float2 v1 = make_float2(acc[mb][nb][2] + bx, acc[mb][nb][3] + by);
            *(float2*)(C + r0) = v0;
            *(float2*)(C + r0 + (size_t)8 * GATES) = v1;
        }
}

// ---------------- activations ----------------
__device__ __forceinline__ float sigmoidf_(float x) {
    return __fdividef(1.0f, 1.0f + __expf(-x));
}
__device__ __forceinline__ float tanhf_(float x) {
    float a = __expf(2.0f * fabsf(x));
    float r = 1.0f - __fdividef(2.0f, 1.0f + a);
    return copysignf(r, x);
}

// ---------------- LSTM recurrence: 96 weights in regs (FFMA2), 32 in smem ----------------
// One CTA per batch element, 512 threads = one per gate.
// w_hh[g][0:96]    -> 48 packed f32x2 register pairs
// w_hh[g][96:128]  -> shared, layout sw[kc][g] float4 (conflict-free)
// smem: sw 64KB + h 512B + gates 2KB
#define REC_SMEM (8 * 512 * 16 + 128 * 4 + 512 * 4)
__global__ __launch_bounds__(512, 1) void lstm_rec_kernel(
    const float* __restrict__ xg, const float* __restrict__ w_hh,
    float* __restrict__ hout, float* __restrict__ hlast, int T)
{
    extern __shared__ float smem[];
    float4* sw = (float4*)smem;                 // 8*512 float4
    float* h_s = smem + 8 * 512 * 4;            // 128 floats
    float* gates = h_s + 128;                   // 512 floats

    const int g = threadIdx.x;
    const int b = blockIdx.x;

    const float4* wrow = (const float4*)(w_hh + (size_t)g * HID);
    u64b wr[48];
#pragma unroll
    for (int i = 0; i < 24; i++) {
        float4 v = wrow[i];                     // k = 4i .. 4i+3
        wr[2 * i]     = pk64(v.x, v.y);
        wr[2 * i + 1] = pk64(v.z, v.w);
    }
#pragma unroll
    for (int kc = 0; kc < 8; kc++) sw[kc * 512 + g] = wrow[24 + kc];   // k = 96..127

    if (g < HID) h_s[g] = 0.0f;
    float c = 0.0f;
    __syncthreads();

    const float* xg_b = xg + ((size_t)b * T) * GATES + g;
    float xg_cur = xg_b[0];

    for (int t = 0; t < T; t++) {
        float xg_nxt = (t + 1 < T) ? xg_b[(size_t)(t + 1) * GATES] : 0.0f;

        u64b acc0 = pk64(xg_cur, 0.0f);
        u64b acc1 = pk64(0.0f, 0.0f);
        const ulonglong2* h2 = (const ulonglong2*)h_s;
        // register-weight half (k = 0..95): broadcast LDS.128 of h + FFMA2
#pragma unroll
        for (int i = 0; i < 24; i++) {
            ulonglong2 hv = h2[i];
            ffma2(acc0, hv.x, wr[2 * i]);
            ffma2(acc1, hv.y, wr[2 * i + 1]);
        }
        // smem-weight half (k = 96..127)
#pragma unroll
        for (int kc = 0; kc < 8; kc++) {
            float4 wv = sw[kc * 512 + g];
            ulonglong2 wu = *reinterpret_cast<ulonglong2*>(&wv);
            ulonglong2 hv = h2[24 + kc];
            ffma2(acc0, hv.x, wu.x);
            ffma2(acc1, hv.y, wu.y);
        }
        float2 a0 = upk64(acc0), a1 = upk64(acc1);
        gates[g] = (a0.x + a0.y) + (a1.x + a1.y);
        __syncthreads();

        if (g < HID) {
            float ig = sigmoidf_(gates[g]);
            float fg = sigmoidf_(gates[HID + g]);
            float gg = tanhf_(gates[2 * HID + g]);
            float og = sigmoidf_(gates[3 * HID + g]);
            c = fg * c + ig * gg;
            float h = og * tanhf_(c);
            h_s[g] = h;
            if (hout) hout[((size_t)b * T + t) * HID + g] = h;
        }
        __syncthreads();
        xg_cur = xg_nxt;
    }
    if (hlast && g < HID) hlast[b * HID + g] = h_s[g];
}

// ---------------- final FC ----------------
__global__ void fc_kernel(const float* __restrict__ hlast, const float* __restrict__ fc_w,
                          const float* __restrict__ fc_b, float* __restrict__ out)
{
    int tid = threadIdx.x;
    int b = tid >> 3;
    int cls = tid & 7;
    const float* hv = hlast + b * HID;
    const float* wv = fc_w + cls * HID;
    float s = fc_b[cls];
#pragma unroll 8
    for (int j = 0; j < HID; j++) s += hv[j] * wv[j];
    out[b * NCLS + cls] = s;
}

// ---------------- launch ----------------
extern "C" void kernel_launch(void* const* d_in, const int* in_sizes, int n_in,
                              void* d_out, int out_size)
{
    const float* x     = (const float*)d_in[0];
    const float* w_ih0 = (const float*)d_in[1];
    const float* w_hh0 = (const float*)d_in[2];
    const float* b_ih0 = (const float*)d_in[3];
    const float* b_hh0 = (const float*)d_in[4];
    const float* w_ih1 = (const float*)d_in[5];
    const float* w_hh1 = (const float*)d_in[6];
    const float* b_ih1 = (const float*)d_in[7];
    const float* b_hh1 = (const float*)d_in[8];
    const float* fc_w  = (const float*)d_in[9];
    const float* fc_b  = (const float*)d_in[10];
    float* out = (float*)d_out;

    float *xg_p = nullptr, *h1_p = nullptr, *hl_p = nullptr;
    __half *as_p = nullptr, *bs0_p = nullptr, *bs1_p = nullptr;
    cudaGetSymbolAddress((void**)&xg_p, g_xg);
    cudaGetSymbolAddress((void**)&h1_p, g_h1);
    cudaGetSymbolAddress((void**)&hl_p, g_hlast);
    cudaGetSymbolAddress((void**)&as_p, g_as);
    cudaGetSymbolAddress((void**)&bs0_p, g_bs0);
    cudaGetSymbolAddress((void**)&bs1_p, g_bs1);

    cudaFuncSetAttribute(lstm_rec_kernel,
                         cudaFuncAttributeMaxDynamicSharedMemorySize, REC_SMEM);
    cudaFuncSetAttribute(gemm_hmma_kernel,
                         cudaFuncAttributeMaxDynamicSharedMemorySize, GEMM_SMEM);

    // weight conversions (tiny)
    conv_b_kernel<<<NCH0 * 512 * 8 / 256, 256>>>(w_ih0, bs0_p, 10);
    conv_b_kernel<<<NCH1 * 512 * 8 / 256, 256>>>(w_ih1, bs1_p, 7);

    // layer 0: x -> split-fp16 tiles -> HMMA GEMM -> recurrence
    conv_a_kernel<<<MTILES * NCH0 * 1024 / 256, 256>>>(x, as_p, NCH0, 10);
    gemm_hmma_kernel<<<MTILES * 2, 512, GEMM_SMEM>>>(as_p, bs0_p, b_ih0, b_hh0, xg_p, NCH0);
    lstm_rec_kernel<<<BATCH, 512, REC_SMEM>>>(xg_p, w_hh0, h1_p, nullptr, SEQT);

    // layer 1: h1 -> split-fp16 tiles -> HMMA GEMM -> recurrence
    conv_a_kernel<<<MTILES * NCH1 * 1024 / 256, 256>>>(h1_p, as_p, NCH1, 7);
    gemm_hmma_kernel<<<MTILES * 2, 512, GEMM_SMEM>>>(as_p, bs1_p, b_ih1, b_hh1, xg_p, NCH1);
    lstm_rec_kernel<<<BATCH, 512, REC_SMEM>>>(xg_p, w_hh1, nullptr, hl_p, SEQT);

    // FC head
    fc_kernel<<<1, BATCH * NCLS>>>(hl_p, fc_w, fc_b, out);
}